// round 9
// baseline (speedup 1.0000x reference)
#include <cuda_runtime.h>
#include <cuda.h>
#include <cuda_bf16.h>
#include <math.h>
#include <stdint.h>

#define K_COMP 64
#define DDIM   256
#define MU_PAD 264      // bf16/row: 132 words -> ldmatrix rows cover all 32 banks
#define NSTAGE 4
#define STAGE_BYTES 2048   // 16 rows x 32 fp32 (128B/row), SW128

// dynamic smem layout (bytes)
#define SMU_OFF   0
#define SMU_BYTES (K_COMP * MU_PAD * 2)          // 33792
#define SC_OFF    SMU_BYTES                      // 4 x 64 floats = 1024
#define MB_OFF    (SC_OFF + 1024)                // 34816: 8 warps x 4 stages x 8B = 256
#define SX_OFF    (MB_OFF + 1024)                // 35840 (1024-aligned)
#define SX_BYTES  (8 * NSTAGE * STAGE_BYTES)     // 65536
#define SMEM_TOTAL (SX_OFF + SX_BYTES)           // 101376

__device__ __align__(16) __nv_bfloat16 g_mu[K_COMP * DDIM];
__device__ float g_kappa[K_COMP];
__device__ float g_logC[K_COMP];
__device__ float g_la[K_COMP];
__device__ float g_C2[K_COMP];

// ---------------- PTX helpers (all plain sm_90-level; NO tcgen05) ----------------
__device__ __forceinline__ void mbar_init(uint32_t a, uint32_t n) {
    asm volatile("mbarrier.init.shared.b64 [%0], %1;" :: "r"(a), "r"(n) : "memory");
}
__device__ __forceinline__ void mbar_expect(uint32_t a, uint32_t bytes) {
    asm volatile("mbarrier.arrive.expect_tx.shared.b64 _, [%0], %1;" :: "r"(a), "r"(bytes) : "memory");
}
__device__ __forceinline__ void mbar_wait(uint32_t a, uint32_t par) {
    asm volatile(
        "{\n\t.reg .pred P;\n"
        "W_%=:\n\t"
        "mbarrier.try_wait.parity.acquire.cta.shared::cta.b64 P, [%0], %1, 0x989680;\n\t"
        "@P bra D_%=;\n\t"
        "bra W_%=;\n"
        "D_%=:\n\t}"
        :: "r"(a), "r"(par) : "memory");
}
__device__ __forceinline__ void tma2d(uint32_t dst, const CUtensorMap* m, int cx, int cy, uint32_t mbar) {
    asm volatile(
        "cp.async.bulk.tensor.2d.shared::cta.global.tile.mbarrier::complete_tx::bytes "
        "[%0], [%1, {%2, %3}], [%4];"
        :: "r"(dst), "l"(m), "r"(cx), "r"(cy), "r"(mbar) : "memory");
}

// ---------------- prep: 64 blocks (one per component), bf16 mu out ----------------
__global__ void prep_fast(const float* __restrict__ alpha_logit,
                          const float* __restrict__ mu_unnorm,
                          const float* __restrict__ log_kappa) {
    __shared__ float sred[4];
    int k = blockIdx.x;
    int tid = threadIdx.x, lane = tid & 31, w = tid >> 5;
    const float s = 0.5f * (float)DDIM - 1.0f;   // 127

    float2 v = reinterpret_cast<const float2*>(mu_unnorm + (size_t)k * DDIM)[tid];
    float ss = v.x * v.x + v.y * v.y;
#pragma unroll
    for (int o = 16; o; o >>= 1) ss += __shfl_xor_sync(0xffffffffu, ss, o);
    if (lane == 0) sred[w] = ss;
    __syncthreads();
    float tot = sred[0] + sred[1] + sred[2] + sred[3];
    float inv = 1.0f / fmaxf(sqrtf(tot), 1e-12f);
    reinterpret_cast<__nv_bfloat162*>(g_mu + (size_t)k * DDIM)[tid] =
        __float22bfloat162_rn(make_float2(v.x * inv, v.y * inv));

    if (w == 0) {
        float a0 = alpha_logit[lane], a1 = alpha_logit[lane + 32];
        float am = fmaxf(a0, a1);
#pragma unroll
        for (int o = 16; o; o >>= 1) am = fmaxf(am, __shfl_xor_sync(0xffffffffu, am, o));
        float ae = expf(a0 - am) + expf(a1 - am);
#pragma unroll
        for (int o = 16; o; o >>= 1) ae += __shfl_xor_sync(0xffffffffu, ae, o);
        float lse = am + logf(ae);

        float kap = expf(log_kappa[k]) + 1e-6f;
        float lk2 = logf(0.5f * kap);
        float cm0 = lgammaf((float)lane + 1.0f)  + lgammaf((float)lane + s + 1.0f);
        float cm1 = lgammaf((float)lane + 33.0f) + lgammaf((float)lane + s + 33.0f);
        float t0 = fmaf(2.0f * lane + s,        lk2, -cm0);
        float t1 = fmaf(2.0f * (lane + 32) + s, lk2, -cm1);
        float tm = fmaxf(t0, t1);
#pragma unroll
        for (int o = 16; o; o >>= 1) tm = fmaxf(tm, __shfl_xor_sync(0xffffffffu, tm, o));
        float ts = expf(t0 - tm) + expf(t1 - tm);
#pragma unroll
        for (int o = 16; o; o >>= 1) ts += __shfl_xor_sync(0xffffffffu, ts, o);

        if (lane == 0) {
            float lbi  = tm + logf(ts);
            float logC = (float)DDIM * (-0.91893853320467274f) + s * logf(kap) - lbi;
            float la   = alpha_logit[k] - lse;
            g_kappa[k] = kap;
            g_logC[k]  = logC;
            g_la[k]    = la;
            g_C2[k]    = logC + la;
        }
    }
}

// ---------------- fast exp: FFMA-only ----------------
__device__ __forceinline__ float fexp(float x) {
    x = fmaxf(x, -87.0f);
    float z = x * 1.4426950408889634f;
    float t = z + 12582912.0f;
    float fi = t - 12582912.0f;
    float f = z - fi;
    int  i  = __float_as_int(t) - 0x4B400000;
    float p = 1.3333558e-3f;
    p = fmaf(p, f, 9.6181291e-3f);
    p = fmaf(p, f, 5.5504109e-2f);
    p = fmaf(p, f, 2.4022651e-1f);
    p = fmaf(p, f, 6.9314718e-1f);
    p = fmaf(p, f, 1.0f);
    return __int_as_float(__float_as_int(p) + (i << 23));
}

__device__ __forceinline__ uint32_t f22bf(float2 v) {
    __nv_bfloat162 b = __float22bfloat162_rn(v);
    return *reinterpret_cast<uint32_t*>(&b);
}

// ---------------- main: per-warp TMA rings + mma.sync, warps fully decoupled ----------
// Each warp owns 16 contiguous rows; streams them with its OWN TMA (box 32x16 fp32,
// SW128) into a private 4-stage ring with private mbarriers. Same warp produces and
// consumes: stage reuse is WAR-safe by dataflow (TMA reissued only after the CVTs that
// consumed the stage). No CTA-wide barriers in the mainloop.
__global__ void __launch_bounds__(256, 2)
vmf_main(const __grid_constant__ CUtensorMap tmap,
         float* __restrict__ out_llh,
         float* __restrict__ out_lp,
         int N) {
    extern __shared__ char smem[];
    __nv_bfloat16* smu = reinterpret_cast<__nv_bfloat16*>(smem + SMU_OFF);
    float* s_kappa = reinterpret_cast<float*>(smem + SC_OFF);
    float* s_logC  = s_kappa + K_COMP;
    float* s_la    = s_logC + K_COMP;
    float* s_C2    = s_la   + K_COMP;

    int tid = threadIdx.x, lane = tid & 31, warp = tid >> 5;
    uint32_t su = (uint32_t)__cvta_generic_to_shared(smem);

    // stage mu with k-pair permutation (slot i <- phys pair (i<4 ? 2i : 2i-7))
    const uint32_t* gmu32 = reinterpret_cast<const uint32_t*>(g_mu);
    for (int idx = tid; idx < K_COMP * (DDIM / 2); idx += 256) {
        int kk = idx >> 7;
        int dp = idx & 127;
        int i  = dp & 7;
        int srcp = (i < 4) ? (2 * i) : (2 * i - 7);
        int src  = (dp & ~7) | srcp;
        reinterpret_cast<uint32_t*>(smu + (size_t)kk * MU_PAD)[dp] = gmu32[kk * 128 + src];
    }
    if (tid < K_COMP) {
        s_kappa[tid] = g_kappa[tid];
        s_logC[tid]  = g_logC[tid];
        s_la[tid]    = g_la[tid];
        s_C2[tid]    = g_C2[tid];
    }
    // init this warp's mbarriers (one thread per warp)
    uint32_t mb = su + MB_OFF + (uint32_t)(warp * NSTAGE * 8);
    if (lane == 0) {
#pragma unroll
        for (int s = 0; s < NSTAGE; s++) mbar_init(mb + s * 8, 1);
    }
    __syncthreads();   // mbarriers + smu visible before any TMA/ldmatrix

    int row0 = blockIdx.x * 128 + warp * 16;   // this warp's 16 rows
    int r  = lane >> 2;        // 0..7
    int cq = (lane & 3) * 2;   // logical col-pair base (epilogue)

    uint32_t sx = su + SX_OFF + (uint32_t)(warp * NSTAGE * STAGE_BYTES);

    // consumer LDS addressing within a stage (SW128: group j of row r at j^(r&7))
    // lane reads rows r and r+8; (r+8)&7 == r&7 -> same xor, +1024B
    uint32_t a_off0 = (uint32_t)(r * 128);     // row r base within stage

    // ldmatrix B lane address (reads permuted smu)
    int li   = lane & 7;
    int csel = (lane >> 3) & 1;
    int tsel = (lane >> 4) & 1;
    uint32_t lm_base = su + SMU_OFF + (uint32_t)(((li + tsel * 8) * MU_PAD + csel * 8) * 2);

    float acc[8][4];
#pragma unroll
    for (int t = 0; t < 8; t++)
#pragma unroll
        for (int j = 0; j < 4; j++) acc[t][j] = 0.0f;

    // prologue: fill all 4 stages with chunks 0..3
    if (lane == 0) {
#pragma unroll
        for (int s = 0; s < NSTAGE; s++) {
            mbar_expect(mb + s * 8, STAGE_BYTES);
            tma2d(sx + s * STAGE_BYTES, &tmap, s * 32, row0, mb + s * 8);
        }
    }

#pragma unroll
    for (int c = 0; c < 8; c++) {
        int st = c & 3;
        mbar_wait(mb + st * 8, (c >> 2) & 1);
        uint32_t sb = sx + (uint32_t)(st * STAGE_BYTES);

        uint32_t fa[2][4];
#pragma unroll
        for (int h = 0; h < 2; h++) {
            int g = ((h * 4 + (lane & 3)) ^ r);         // swizzled 16B group
            uint32_t a0addr = sb + a_off0 + (uint32_t)(g << 4);
            float4 A0, A1;
            asm volatile("ld.shared.v4.f32 {%0,%1,%2,%3}, [%4];"
                         : "=f"(A0.x), "=f"(A0.y), "=f"(A0.z), "=f"(A0.w) : "r"(a0addr));
            asm volatile("ld.shared.v4.f32 {%0,%1,%2,%3}, [%4];"
                         : "=f"(A1.x), "=f"(A1.y), "=f"(A1.z), "=f"(A1.w) : "r"(a0addr + 1024));
            fa[h][0] = f22bf(make_float2(A0.x, A0.y));
            fa[h][1] = f22bf(make_float2(A1.x, A1.y));
            fa[h][2] = f22bf(make_float2(A0.z, A0.w));
            fa[h][3] = f22bf(make_float2(A1.z, A1.w));
        }

        // stage data now in registers -> safe to reissue TMA into this stage
        if (c < 4 && lane == 0) {
            int c2 = c + 4;
            mbar_expect(mb + st * 8, STAGE_BYTES);
            tma2d(sb, &tmap, c2 * 32, row0, mb + st * 8);
        }

#pragma unroll
        for (int h = 0; h < 2; h++) {
            int kk = c * 2 + h;
            uint32_t lmaddr = lm_base + (uint32_t)(kk * 32);
#pragma unroll
            for (int tp = 0; tp < 4; tp++) {
                uint32_t b0, b1, b2, b3;
                asm volatile(
                    "ldmatrix.sync.aligned.m8n8.x4.shared.b16 {%0,%1,%2,%3}, [%4];\n"
                    : "=r"(b0), "=r"(b1), "=r"(b2), "=r"(b3)
                    : "r"(lmaddr + (uint32_t)(tp * 16 * MU_PAD * 2)));
                asm volatile(
                    "mma.sync.aligned.m16n8k16.row.col.f32.bf16.bf16.f32 "
                    "{%0,%1,%2,%3}, {%4,%5,%6,%7}, {%8,%9}, {%0,%1,%2,%3};\n"
                    : "+f"(acc[tp*2][0]), "+f"(acc[tp*2][1]), "+f"(acc[tp*2][2]), "+f"(acc[tp*2][3])
                    : "r"(fa[h][0]), "r"(fa[h][1]), "r"(fa[h][2]), "r"(fa[h][3]), "r"(b0), "r"(b1));
                asm volatile(
                    "mma.sync.aligned.m16n8k16.row.col.f32.bf16.bf16.f32 "
                    "{%0,%1,%2,%3}, {%4,%5,%6,%7}, {%8,%9}, {%0,%1,%2,%3};\n"
                    : "+f"(acc[tp*2+1][0]), "+f"(acc[tp*2+1][1]), "+f"(acc[tp*2+1][2]), "+f"(acc[tp*2+1][3])
                    : "r"(fa[h][0]), "r"(fa[h][1]), "r"(fa[h][2]), "r"(fa[h][3]), "r"(b2), "r"(b3));
            }
        }
    }

    // ---- epilogue: log_prob + per-row logsumexp (R4 form, direct stores) ----
    int gr0 = row0 + r, gr1 = gr0 + 8;
    float2* lp0 = reinterpret_cast<float2*>(out_lp + (size_t)gr0 * K_COMP);
    float2* lp1 = reinterpret_cast<float2*>(out_lp + (size_t)gr1 * K_COMP);

    float m0 = -1e30f, m1 = -1e30f;
#pragma unroll
    for (int t = 0; t < 8; t++) {
        int cc = t * 8 + cq;
        float k0 = s_kappa[cc], k1 = s_kappa[cc + 1];
        float lc0 = s_logC[cc], lc1 = s_logC[cc + 1];
        float la0 = s_la[cc],   la1 = s_la[cc + 1];
        float lp00 = fmaf(k0, acc[t][0], lc0);
        float lp01 = fmaf(k1, acc[t][1], lc1);
        float lp10 = fmaf(k0, acc[t][2], lc0);
        float lp11 = fmaf(k1, acc[t][3], lc1);
        __stcs(lp0 + (cc >> 1), make_float2(lp00, lp01));
        __stcs(lp1 + (cc >> 1), make_float2(lp10, lp11));
        m0 = fmaxf(m0, fmaxf(lp00 + la0, lp01 + la1));
        m1 = fmaxf(m1, fmaxf(lp10 + la0, lp11 + la1));
    }
    m0 = fmaxf(m0, __shfl_xor_sync(0xffffffffu, m0, 1));
    m0 = fmaxf(m0, __shfl_xor_sync(0xffffffffu, m0, 2));
    m1 = fmaxf(m1, __shfl_xor_sync(0xffffffffu, m1, 1));
    m1 = fmaxf(m1, __shfl_xor_sync(0xffffffffu, m1, 2));

    float s0 = 0.0f, s1 = 0.0f;
#pragma unroll
    for (int t = 0; t < 8; t++) {
        int cc = t * 8 + cq;
        float k0 = s_kappa[cc], k1 = s_kappa[cc + 1];
        float c20 = s_C2[cc],   c21 = s_C2[cc + 1];
        s0 += fexp(fmaf(k0, acc[t][0], c20) - m0);
        s0 += fexp(fmaf(k1, acc[t][1], c21) - m0);
        s1 += fexp(fmaf(k0, acc[t][2], c20) - m1);
        s1 += fexp(fmaf(k1, acc[t][3], c21) - m1);
    }
    s0 += __shfl_xor_sync(0xffffffffu, s0, 1);
    s0 += __shfl_xor_sync(0xffffffffu, s0, 2);
    s1 += __shfl_xor_sync(0xffffffffu, s1, 1);
    s1 += __shfl_xor_sync(0xffffffffu, s1, 2);

    if ((lane & 3) == 0) {
        out_llh[gr0] = m0 + __logf(s0);
        out_llh[gr1] = m1 + __logf(s1);
    }
}

// ---------------- launch ----------------
typedef CUresult (*PFN_encodeTiled)(CUtensorMap*, CUtensorMapDataType, cuuint32_t, void*,
                                    const cuuint64_t*, const cuuint64_t*, const cuuint32_t*,
                                    const cuuint32_t*, CUtensorMapInterleave, CUtensorMapSwizzle,
                                    CUtensorMapL2promotion, CUtensorMapFloatOOBfill);

extern "C" void kernel_launch(void* const* d_in, const int* in_sizes, int n_in,
                              void* d_out, int out_size) {
    const float* x           = (const float*)d_in[0];
    const float* alpha_logit = (const float*)d_in[1];
    const float* mu_unnorm   = (const float*)d_in[2];
    const float* log_kappa   = (const float*)d_in[3];

    int K = in_sizes[1];            // 64
    int D = in_sizes[2] / K;        // 256
    int N = in_sizes[0] / D;        // 262144
    (void)n_in; (void)out_size;

    float* out = (float*)d_out;
    float* llh = out;               // (N,)
    float* lp  = out + (size_t)N;   // (N, K)

    // TMA descriptor for x: [DDIM, N] fp32, box [32, 16], SW128
    PFN_encodeTiled enc = nullptr;
    cudaDriverEntryPointQueryResult qres;
    cudaGetDriverEntryPoint("cuTensorMapEncodeTiled", (void**)&enc, cudaEnableDefault, &qres);
    CUtensorMap tmap;
    cuuint64_t dims[2]    = {(cuuint64_t)DDIM, (cuuint64_t)N};
    cuuint64_t strides[1] = {(cuuint64_t)DDIM * 4};
    cuuint32_t box[2]     = {32, 16};
    cuuint32_t es[2]      = {1, 1};
    enc(&tmap, CU_TENSOR_MAP_DATA_TYPE_FLOAT32, 2, (void*)x, dims, strides, box, es,
        CU_TENSOR_MAP_INTERLEAVE_NONE, CU_TENSOR_MAP_SWIZZLE_128B,
        CU_TENSOR_MAP_L2_PROMOTION_L2_128B, CU_TENSOR_MAP_FLOAT_OOB_FILL_NONE);

    cudaFuncSetAttribute(vmf_main, cudaFuncAttributeMaxDynamicSharedMemorySize, SMEM_TOTAL);

    prep_fast<<<K_COMP, 128>>>(alpha_logit, mu_unnorm, log_kappa);
    vmf_main<<<N / 128, 256, SMEM_TOTAL>>>(tmap, llh, lp, N);
}

// round 10
// speedup vs baseline: 1.3579x; 1.3579x over previous
#include <cuda_runtime.h>
#include <cuda_bf16.h>
#include <math.h>
#include <stdint.h>

#define K_COMP 64
#define DDIM   256
#define MU_PAD 264     // bf16/row: 132 words -> ldmatrix rows cover all 32 banks

__device__ __align__(16) __nv_bfloat16 g_mu[K_COMP * DDIM];
__device__ float g_kappa[K_COMP];
__device__ float g_logC[K_COMP];
__device__ float g_la[K_COMP];
__device__ float g_C2[K_COMP];

// ---------------- prep: 64 blocks (one per component) ----------------
__global__ void prep_fast(const float* __restrict__ alpha_logit,
                          const float* __restrict__ mu_unnorm,
                          const float* __restrict__ log_kappa) {
    __shared__ float sred[4];
    int k = blockIdx.x;
    int tid = threadIdx.x, lane = tid & 31, w = tid >> 5;
    const float s = 0.5f * (float)DDIM - 1.0f;   // 127

    float2 v = reinterpret_cast<const float2*>(mu_unnorm + (size_t)k * DDIM)[tid];
    float ss = v.x * v.x + v.y * v.y;
#pragma unroll
    for (int o = 16; o; o >>= 1) ss += __shfl_xor_sync(0xffffffffu, ss, o);
    if (lane == 0) sred[w] = ss;
    __syncthreads();
    float tot = sred[0] + sred[1] + sred[2] + sred[3];
    float inv = 1.0f / fmaxf(sqrtf(tot), 1e-12f);
    reinterpret_cast<__nv_bfloat162*>(g_mu + (size_t)k * DDIM)[tid] =
        __float22bfloat162_rn(make_float2(v.x * inv, v.y * inv));

    if (w == 0) {
        float a0 = alpha_logit[lane], a1 = alpha_logit[lane + 32];
        float am = fmaxf(a0, a1);
#pragma unroll
        for (int o = 16; o; o >>= 1) am = fmaxf(am, __shfl_xor_sync(0xffffffffu, am, o));
        float ae = expf(a0 - am) + expf(a1 - am);
#pragma unroll
        for (int o = 16; o; o >>= 1) ae += __shfl_xor_sync(0xffffffffu, ae, o);
        float lse = am + logf(ae);

        float kap = expf(log_kappa[k]) + 1e-6f;
        float lk2 = logf(0.5f * kap);
        float cm0 = lgammaf((float)lane + 1.0f)  + lgammaf((float)lane + s + 1.0f);
        float cm1 = lgammaf((float)lane + 33.0f) + lgammaf((float)lane + s + 33.0f);
        float t0 = fmaf(2.0f * lane + s,        lk2, -cm0);
        float t1 = fmaf(2.0f * (lane + 32) + s, lk2, -cm1);
        float tm = fmaxf(t0, t1);
#pragma unroll
        for (int o = 16; o; o >>= 1) tm = fmaxf(tm, __shfl_xor_sync(0xffffffffu, tm, o));
        float ts = expf(t0 - tm) + expf(t1 - tm);
#pragma unroll
        for (int o = 16; o; o >>= 1) ts += __shfl_xor_sync(0xffffffffu, ts, o);

        if (lane == 0) {
            float lbi  = tm + logf(ts);
            float logC = (float)DDIM * (-0.91893853320467274f) + s * logf(kap) - lbi;
            float la   = alpha_logit[k] - lse;
            g_kappa[k] = kap;
            g_logC[k]  = logC;
            g_la[k]    = la;
            g_C2[k]    = logC + la;
        }
    }
}

// ---------------- fast exp: FFMA-only ----------------
__device__ __forceinline__ float fexp(float x) {
    x = fmaxf(x, -87.0f);
    float z = x * 1.4426950408889634f;
    float t = z + 12582912.0f;
    float fi = t - 12582912.0f;
    float f = z - fi;
    int  i  = __float_as_int(t) - 0x4B400000;
    float p = 1.3333558e-3f;
    p = fmaf(p, f, 9.6181291e-3f);
    p = fmaf(p, f, 5.5504109e-2f);
    p = fmaf(p, f, 2.4022651e-1f);
    p = fmaf(p, f, 6.9314718e-1f);
    p = fmaf(p, f, 1.0f);
    return __int_as_float(__float_as_int(p) + (i << 23));
}

__device__ __forceinline__ uint32_t f22bf(float2 v) {
    __nv_bfloat162 b = __float22bfloat162_rn(v);
    return *reinterpret_cast<uint32_t*>(&b);
}

// ---------------- main: 32 rows/warp — 4 ldmatrix feed 16 MMAs (LDSM wf/row halved) ---
// Loads stay LDG.128 (permuted-k layout, R4); reload-after-consume keeps depth-2 with
// only 32 buffer regs. Two row-tiles (rows r/r+8 and r+16/r+24) share every B fragment.
__global__ void __launch_bounds__(256, 2)
vmf_main(const float* __restrict__ x,
         float* __restrict__ out_llh,
         float* __restrict__ out_lp,
         int N) {
    __shared__ __align__(16) __nv_bfloat16 smu[K_COMP][MU_PAD];
    __shared__ float s_kappa[K_COMP], s_logC[K_COMP], s_la[K_COMP], s_C2[K_COMP];

    int tid = threadIdx.x;

    // stage mu with k-pair permutation (slot i <- phys pair (i<4 ? 2i : 2i-7))
    const uint32_t* gmu32 = reinterpret_cast<const uint32_t*>(g_mu);
    for (int idx = tid; idx < K_COMP * (DDIM / 2); idx += 256) {
        int kk = idx >> 7;
        int dp = idx & 127;
        int i  = dp & 7;
        int srcp = (i < 4) ? (2 * i) : (2 * i - 7);
        int src  = (dp & ~7) | srcp;
        reinterpret_cast<uint32_t*>(&smu[kk][0])[dp] = gmu32[kk * 128 + src];
    }
    if (tid < K_COMP) {
        s_kappa[tid] = g_kappa[tid];
        s_logC[tid]  = g_logC[tid];
        s_la[tid]    = g_la[tid];
        s_C2[tid]    = g_C2[tid];
    }
    __syncthreads();

    int warp = tid >> 5, lane = tid & 31;
    int row0 = blockIdx.x * 256 + warp * 32;   // 32 rows per warp

    int r  = lane >> 2;        // 0..7
    int cq = (lane & 3) * 2;   // logical col-pair base (epilogue)

    const float* p0 = x + (size_t)(row0 + r) * DDIM + (lane & 3) * 4;

    // ldmatrix B lane address (reads permuted smu)
    uint32_t smu_base = (uint32_t)__cvta_generic_to_shared(&smu[0][0]);
    int li   = lane & 7;
    int csel = (lane >> 3) & 1;
    int tsel = (lane >> 4) & 1;
    uint32_t lm_base = smu_base + (uint32_t)(((li + tsel * 8) * MU_PAD + csel * 8) * 2);

    float acc0[8][4], acc1[8][4];
#pragma unroll
    for (int t = 0; t < 8; t++)
#pragma unroll
        for (int j = 0; j < 4; j++) { acc0[t][j] = 0.0f; acc1[t][j] = 0.0f; }

    // 2-buffer depth-2 prefetch; buf[b][g] = rows r + 8g
    float4 buf[2][4];
#pragma unroll
    for (int c = 0; c < 2; c++)
#pragma unroll
        for (int g = 0; g < 4; g++)
            buf[c][g] = __ldcs(reinterpret_cast<const float4*>(p0 + c * 16 + g * 8 * DDIM));

#pragma unroll
    for (int kk = 0; kk < 16; kk++) {
        int b = kk & 1;
        float4 A0 = buf[b][0], A1 = buf[b][1], A2 = buf[b][2], A3 = buf[b][3];

        // row-tile 0: rows r, r+8
        uint32_t u0 = f22bf(make_float2(A0.x, A0.y));
        uint32_t u1 = f22bf(make_float2(A1.x, A1.y));
        uint32_t u2 = f22bf(make_float2(A0.z, A0.w));
        uint32_t u3 = f22bf(make_float2(A1.z, A1.w));
        // row-tile 1: rows r+16, r+24
        uint32_t v0 = f22bf(make_float2(A2.x, A2.y));
        uint32_t v1 = f22bf(make_float2(A3.x, A3.y));
        uint32_t v2 = f22bf(make_float2(A2.z, A2.w));
        uint32_t v3 = f22bf(make_float2(A3.z, A3.w));

        // buf[b] dead -> reload with chunk kk+2 (keeps depth-2 in flight)
        if (kk < 14) {
            int off = (kk + 2) * 16;
#pragma unroll
            for (int g = 0; g < 4; g++)
                buf[b][g] = __ldcs(reinterpret_cast<const float4*>(p0 + off + g * 8 * DDIM));
        }

        uint32_t lmaddr = lm_base + (uint32_t)(kk * 32);
#pragma unroll
        for (int tp = 0; tp < 4; tp++) {
            uint32_t b0, b1, b2, b3;
            asm volatile(
                "ldmatrix.sync.aligned.m8n8.x4.shared.b16 {%0,%1,%2,%3}, [%4];\n"
                : "=r"(b0), "=r"(b1), "=r"(b2), "=r"(b3)
                : "r"(lmaddr + (uint32_t)(tp * 16 * MU_PAD * 2)));
            asm volatile(
                "mma.sync.aligned.m16n8k16.row.col.f32.bf16.bf16.f32 "
                "{%0,%1,%2,%3}, {%4,%5,%6,%7}, {%8,%9}, {%0,%1,%2,%3};\n"
                : "+f"(acc0[tp*2][0]), "+f"(acc0[tp*2][1]), "+f"(acc0[tp*2][2]), "+f"(acc0[tp*2][3])
                : "r"(u0), "r"(u1), "r"(u2), "r"(u3), "r"(b0), "r"(b1));
            asm volatile(
                "mma.sync.aligned.m16n8k16.row.col.f32.bf16.bf16.f32 "
                "{%0,%1,%2,%3}, {%4,%5,%6,%7}, {%8,%9}, {%0,%1,%2,%3};\n"
                : "+f"(acc0[tp*2+1][0]), "+f"(acc0[tp*2+1][1]), "+f"(acc0[tp*2+1][2]), "+f"(acc0[tp*2+1][3])
                : "r"(u0), "r"(u1), "r"(u2), "r"(u3), "r"(b2), "r"(b3));
            asm volatile(
                "mma.sync.aligned.m16n8k16.row.col.f32.bf16.bf16.f32 "
                "{%0,%1,%2,%3}, {%4,%5,%6,%7}, {%8,%9}, {%0,%1,%2,%3};\n"
                : "+f"(acc1[tp*2][0]), "+f"(acc1[tp*2][1]), "+f"(acc1[tp*2][2]), "+f"(acc1[tp*2][3])
                : "r"(v0), "r"(v1), "r"(v2), "r"(v3), "r"(b0), "r"(b1));
            asm volatile(
                "mma.sync.aligned.m16n8k16.row.col.f32.bf16.bf16.f32 "
                "{%0,%1,%2,%3}, {%4,%5,%6,%7}, {%8,%9}, {%0,%1,%2,%3};\n"
                : "+f"(acc1[tp*2+1][0]), "+f"(acc1[tp*2+1][1]), "+f"(acc1[tp*2+1][2]), "+f"(acc1[tp*2+1][3])
                : "r"(v0), "r"(v1), "r"(v2), "r"(v3), "r"(b2), "r"(b3));
        }
    }

    // ---- epilogue: two row-groups, R4 form each ----
#pragma unroll
    for (int G = 0; G < 2; G++) {
        int gr0 = row0 + G * 16 + r, gr1 = gr0 + 8;
        float2* lp0 = reinterpret_cast<float2*>(out_lp + (size_t)gr0 * K_COMP);
        float2* lp1 = reinterpret_cast<float2*>(out_lp + (size_t)gr1 * K_COMP);

        float m0 = -1e30f, m1 = -1e30f;
#pragma unroll
        for (int t = 0; t < 8; t++) {
            int cc = t * 8 + cq;
            float a0 = G ? acc1[t][0] : acc0[t][0];
            float a1 = G ? acc1[t][1] : acc0[t][1];
            float a2 = G ? acc1[t][2] : acc0[t][2];
            float a3 = G ? acc1[t][3] : acc0[t][3];
            float k0 = s_kappa[cc], k1 = s_kappa[cc + 1];
            float lc0 = s_logC[cc], lc1 = s_logC[cc + 1];
            float la0 = s_la[cc],   la1 = s_la[cc + 1];
            float lp00 = fmaf(k0, a0, lc0);
            float lp01 = fmaf(k1, a1, lc1);
            float lp10 = fmaf(k0, a2, lc0);
            float lp11 = fmaf(k1, a3, lc1);
            __stcs(lp0 + (cc >> 1), make_float2(lp00, lp01));
            __stcs(lp1 + (cc >> 1), make_float2(lp10, lp11));
            m0 = fmaxf(m0, fmaxf(lp00 + la0, lp01 + la1));
            m1 = fmaxf(m1, fmaxf(lp10 + la0, lp11 + la1));
        }
        m0 = fmaxf(m0, __shfl_xor_sync(0xffffffffu, m0, 1));
        m0 = fmaxf(m0, __shfl_xor_sync(0xffffffffu, m0, 2));
        m1 = fmaxf(m1, __shfl_xor_sync(0xffffffffu, m1, 1));
        m1 = fmaxf(m1, __shfl_xor_sync(0xffffffffu, m1, 2));

        float s0 = 0.0f, s1 = 0.0f;
#pragma unroll
        for (int t = 0; t < 8; t++) {
            int cc = t * 8 + cq;
            float a0 = G ? acc1[t][0] : acc0[t][0];
            float a1 = G ? acc1[t][1] : acc0[t][1];
            float a2 = G ? acc1[t][2] : acc0[t][2];
            float a3 = G ? acc1[t][3] : acc0[t][3];
            float k0 = s_kappa[cc], k1 = s_kappa[cc + 1];
            float c20 = s_C2[cc],   c21 = s_C2[cc + 1];
            s0 += fexp(fmaf(k0, a0, c20) - m0);
            s0 += fexp(fmaf(k1, a1, c21) - m0);
            s1 += fexp(fmaf(k0, a2, c20) - m1);
            s1 += fexp(fmaf(k1, a3, c21) - m1);
        }
        s0 += __shfl_xor_sync(0xffffffffu, s0, 1);
        s0 += __shfl_xor_sync(0xffffffffu, s0, 2);
        s1 += __shfl_xor_sync(0xffffffffu, s1, 1);
        s1 += __shfl_xor_sync(0xffffffffu, s1, 2);

        if ((lane & 3) == 0) {
            out_llh[gr0] = m0 + __logf(s0);
            out_llh[gr1] = m1 + __logf(s1);
        }
    }
}

// ---------------- launch -----------------------------------------------------------
extern "C" void kernel_launch(void* const* d_in, const int* in_sizes, int n_in,
                              void* d_out, int out_size) {
    const float* x           = (const float*)d_in[0];
    const float* alpha_logit = (const float*)d_in[1];
    const float* mu_unnorm   = (const float*)d_in[2];
    const float* log_kappa   = (const float*)d_in[3];

    int K = in_sizes[1];            // 64
    int D = in_sizes[2] / K;        // 256
    int N = in_sizes[0] / D;        // 262144
    (void)n_in; (void)out_size;

    float* out = (float*)d_out;
    float* llh = out;               // (N,)
    float* lp  = out + (size_t)N;   // (N, K)

    prep_fast<<<K_COMP, 128>>>(alpha_logit, mu_unnorm, log_kappa);
    vmf_main<<<N / 256, 256>>>(x, llh, lp, N);
}